// round 12
// baseline (speedup 1.0000x reference)
#include <cuda_runtime.h>
#include <cuda_bf16.h>

// Problem constants (fixed by reference setup_inputs)
#define BATCH   16
#define NHEAD   16
#define HDIM    64
#define HW      4096                   // H*W
#define ROWQ    (HW / 4)               // float4s per row = 1024
#define BROWS   (NHEAD * HDIM)         // rows per batch = 1024
#define NROWS   (BATCH * BROWS)        // 16384 rows
#define LSEQ    16                     // sequence length (= nH)
#define BN      4                      // bottleneck dim
#define MHA_H   2
#define DH      2

#define TPB     256                    // threads per block; 16 floats/thread

// Scratch + per-batch barrier state (no allocations allowed)
__device__ float    g_pooled[NROWS];
__device__ unsigned g_cnt [BATCH];     // arrivals, self-resetting
__device__ unsigned g_done[BATCH];     // monotonic release counters

__global__ __launch_bounds__(TPB, 8) void fused_kernel(
    const float* __restrict__ x,   float* __restrict__ out,
    const float* __restrict__ cw,  const float* __restrict__ cb,
    const float* __restrict__ ipw, const float* __restrict__ ipb,
    const float* __restrict__ opw, const float* __restrict__ opb,
    const float* __restrict__ ew,  const float* __restrict__ eb,
    const float* __restrict__ lnw, const float* __restrict__ lnb,
    const float* __restrict__ gate)
{
    const int grow  = blockIdx.x;           // global row id
    const int b     = grow >> 10;           // batch
    const int my_nH = (grow >> 6) & 15;
    const int my_hd = grow & 63;
    const int t     = threadIdx.x;

    // --- shared memory ------------------------------------------------------
    __shared__ float s_row[HW];              // this block's x row (16 KB)
    __shared__ float sp   [LSEQ * HDIM];     // pooled for this batch
    __shared__ float s_xc [LSEQ][BN];
    __shared__ float s_qkv[LSEQ][3 * BN];
    __shared__ float s_sc [MHA_H * LSEQ][LSEQ];
    __shared__ float s_ov [LSEQ][BN];
    __shared__ float s_xat[LSEQ][BN];
    __shared__ float s_dval;                 // delta scalar for this row
    __shared__ float ws[8];
    __shared__ float wred[2];
    // weights
    __shared__ float s_cw [BN * HDIM], s_cb [BN];
    __shared__ float s_ipw[3 * BN * BN], s_ipb[3 * BN];
    __shared__ float s_opw[BN * BN],  s_opb[BN];
    __shared__ float s_ew [HDIM * BN], s_eb [HDIM];
    __shared__ float s_lnw[HDIM], s_lnb[HDIM];
    __shared__ float s_gate;

    // snapshot of this batch's release counter (before our own arrival)
    unsigned target = 0;
    if (t == 0) target = *(volatile unsigned*)&g_done[b] + 1u;

    // --- weights -> smem (overlaps with row load below) ----------------------
    if (t < BN * HDIM)   s_cw[t]  = cw[t];
    if (t < HDIM * BN)   s_ew[t]  = ew[t];
    if (t < 3 * BN * BN) s_ipw[t] = ipw[t];
    if (t < 3 * BN)      s_ipb[t] = ipb[t];
    if (t < BN * BN)     s_opw[t] = opw[t];
    if (t < BN)        { s_opb[t] = opb[t]; s_cb[t] = cb[t]; }
    if (t < HDIM)      { s_eb[t] = eb[t]; s_lnw[t] = lnw[t]; s_lnb[t] = lnb[t]; }
    if (t == 0)          s_gate = gate[0];

    // --- load row into smem (x dead afterwards -> __ldcs) + mean -------------
    const float4* __restrict__ xr =
        reinterpret_cast<const float4*>(x) + (size_t)grow * ROWQ;
    float4* __restrict__ sr4 = reinterpret_cast<float4*>(s_row);

    float s = 0.f;
#pragma unroll
    for (int i = 0; i < 4; i++) {
        float4 v = __ldcs(xr + t + i * TPB);
        sr4[t + i * TPB] = v;
        s += (v.x + v.y) + (v.z + v.w);
    }
#pragma unroll
    for (int off = 16; off; off >>= 1)
        s += __shfl_xor_sync(0xffffffffu, s, off);
    if ((t & 31) == 0) ws[t >> 5] = s;
    __syncthreads();

    // --- publish mean + arrive at this batch's barrier -----------------------
    if (t == 0) {
        float tot = 0.f;
#pragma unroll
        for (int w = 0; w < 8; w++) tot += ws[w];
        g_pooled[grow] = tot * (1.0f / (float)HW);
        __threadfence();
        unsigned old = atomicAdd(&g_cnt[b], 1u);
        if (old == BROWS - 1) {              // last arriver: reset + release
            g_cnt[b] = 0;
            __threadfence();
            atomicAdd(&g_done[b], 1u);
        } else {
            while ((int)(*(volatile unsigned*)&g_done[b] - target) < 0)
                __nanosleep(64);
        }
        __threadfence();
    }
    __syncthreads();

    // --- middle (redundant per block, tiny) ----------------------------------
    const float* __restrict__ pb = g_pooled + (size_t)b * (LSEQ * HDIM);
#pragma unroll
    for (int i = 0; i < 4; i++)
        sp[t + i * TPB] = __ldcg(pb + t + i * TPB);
    __syncthreads();

    // compress: 64 outputs (l,e)
    if (t < LSEQ * BN) {
        const int l = t >> 2, e = t & 3;
        float acc = s_cb[e];
#pragma unroll 8
        for (int k = 0; k < HDIM; k++)
            acc = fmaf(sp[l * HDIM + k], s_cw[e * HDIM + k], acc);
        s_xc[l][e] = acc;
    }
    __syncthreads();

    // qkv: 192 outputs
    if (t < LSEQ * 3 * BN) {
        const int l = t / (3 * BN), e = t % (3 * BN);
        float acc = s_ipb[e];
#pragma unroll
        for (int k = 0; k < BN; k++)
            acc = fmaf(s_xc[l][k], s_ipw[e * BN + k], acc);
        s_qkv[l][e] = acc;
    }
    __syncthreads();

    // attention: 2 heads x 16 queries
    if (t < MHA_H * LSEQ) {
        const int h = t / LSEQ, q = t % LSEQ;
        const float scale = rsqrtf((float)DH);
        const float q0 = s_qkv[q][h * DH + 0];
        const float q1 = s_qkv[q][h * DH + 1];
        float m = -1e30f;
#pragma unroll
        for (int k = 0; k < LSEQ; k++) {
            float sc = (q0 * s_qkv[k][BN + h * DH + 0] +
                        q1 * s_qkv[k][BN + h * DH + 1]) * scale;
            s_sc[t][k] = sc;
            m = fmaxf(m, sc);
        }
        float den = 0.f;
#pragma unroll
        for (int k = 0; k < LSEQ; k++) {
            float e2 = __expf(s_sc[t][k] - m);
            s_sc[t][k] = e2;
            den += e2;
        }
        const float inv = 1.0f / den;
        float o0 = 0.f, o1 = 0.f;
#pragma unroll
        for (int k = 0; k < LSEQ; k++) {
            const float a = s_sc[t][k] * inv;
            o0 = fmaf(a, s_qkv[k][2 * BN + h * DH + 0], o0);
            o1 = fmaf(a, s_qkv[k][2 * BN + h * DH + 1], o1);
        }
        s_ov[q][h * DH + 0] = o0;
        s_ov[q][h * DH + 1] = o1;
    }
    __syncthreads();

    // out_proj: 64 outputs
    if (t < LSEQ * BN) {
        const int l = t >> 2, e = t & 3;
        float acc = s_opb[e];
#pragma unroll
        for (int k = 0; k < BN; k++)
            acc = fmaf(s_ov[l][k], s_opw[e * BN + k], acc);
        s_xat[l][e] = acc;
    }
    __syncthreads();

    // expand + residual + gate + LN for l = my_nH (threads 0..63)
    {
        const float g = s_gate;
        float y = 0.f, res = 0.f;
        if (t < HDIM) {
            float xe = s_eb[t];
#pragma unroll
            for (int k = 0; k < BN; k++)
                xe = fmaf(s_xat[my_nH][k], s_ew[t * BN + k], xe);
            res = sp[my_nH * HDIM + t];
            y = fmaf(g, xe, res);
        }
        float sm = (t < HDIM) ? y : 0.f;
#pragma unroll
        for (int off = 16; off; off >>= 1)
            sm += __shfl_xor_sync(0xffffffffu, sm, off);
        if (t == 0 || t == 32) wred[t >> 5] = sm;
        __syncthreads();
        const float mu = (wred[0] + wred[1]) * (1.0f / (float)HDIM);
        __syncthreads();

        const float dy = (t < HDIM) ? (y - mu) : 0.f;
        float s2 = dy * dy;
#pragma unroll
        for (int off = 16; off; off >>= 1)
            s2 += __shfl_xor_sync(0xffffffffu, s2, off);
        if (t == 0 || t == 32) wred[t >> 5] = s2;
        __syncthreads();
        const float var = (wred[0] + wred[1]) * (1.0f / (float)HDIM);
        if (t == my_hd) {
            const float ln = dy * rsqrtf(var + 1e-5f) * s_lnw[t] + s_lnb[t];
            s_dval = ln - res;
        }
    }
    __syncthreads();

    // --- write phase: out = smem row + delta (no x re-read at all) -----------
    const float d = s_dval;
    float4* __restrict__ orow =
        reinterpret_cast<float4*>(out) + (size_t)grow * ROWQ;
#pragma unroll
    for (int i = 0; i < 4; i++) {
        float4 v = sr4[t + i * TPB];
        v.x += d; v.y += d; v.z += d; v.w += d;
        __stcs(orow + t + i * TPB, v);
    }
}

// ---------------------------------------------------------------------------
extern "C" void kernel_launch(void* const* d_in, const int* in_sizes, int n_in,
                              void* d_out, int out_size) {
    const float* x   = (const float*)d_in[0];
    const float* cw  = (const float*)d_in[1];
    const float* cb  = (const float*)d_in[2];
    const float* ipw = (const float*)d_in[3];
    const float* ipb = (const float*)d_in[4];
    const float* opw = (const float*)d_in[5];
    const float* opb = (const float*)d_in[6];
    const float* ew  = (const float*)d_in[7];
    const float* eb  = (const float*)d_in[8];
    const float* lnw = (const float*)d_in[9];
    const float* lnb = (const float*)d_in[10];
    const float* gt  = (const float*)d_in[11];
    float* out = (float*)d_out;

    fused_kernel<<<NROWS, TPB>>>(x, out, cw, cb, ipw, ipb, opw, opb,
                                 ew, eb, lnw, lnb, gt);
}

// round 13
// speedup vs baseline: 1.1890x; 1.1890x over previous
#include <cuda_runtime.h>
#include <cuda_bf16.h>

// Problem constants (fixed by reference setup_inputs)
#define BATCH   16
#define NHEAD   16
#define HDIM    64
#define HW      4096                   // H*W
#define ROWQ    (HW / 4)               // float4s per row = 1024
#define BROWS   (NHEAD * HDIM)         // rows per batch = 1024
#define NROWS   (BATCH * BROWS)        // 16384 rows
#define LSEQ    16                     // sequence length (= nH)
#define BN      4                      // bottleneck dim
#define MHA_H   2
#define DH      2

#define GRID    1024                   // one co-resident wave (<= 8/SM x 148)
#define TPB     256

// Scratch + per-batch sync state (no allocations allowed)
__device__ float    g_pooled[NROWS];
__device__ float    g_delta [NROWS];
__device__ unsigned g_cnt [BATCH];     // arrivals, self-resetting
__device__ unsigned g_done[BATCH];     // monotonic release counters

__global__ __launch_bounds__(TPB, 8) void fused_kernel(
    const float* __restrict__ x,   float* __restrict__ out,
    const float* __restrict__ cw,  const float* __restrict__ cb,
    const float* __restrict__ ipw, const float* __restrict__ ipb,
    const float* __restrict__ opw, const float* __restrict__ opb,
    const float* __restrict__ ew,  const float* __restrict__ eb,
    const float* __restrict__ lnw, const float* __restrict__ lnb,
    const float* __restrict__ gate)
{
    const int bid = blockIdx.x;        // row slot within each batch
    const int t   = threadIdx.x;

    // --- shared memory -------------------------------------------------------
    __shared__ float sp   [LSEQ * HDIM];
    __shared__ float s_xc [LSEQ][BN];
    __shared__ float s_qkv[LSEQ][3 * BN];
    __shared__ float s_sc [MHA_H * LSEQ][LSEQ];
    __shared__ float s_ov [LSEQ][BN];
    __shared__ float s_xat[LSEQ][BN];
    __shared__ float ws[8];
    __shared__ float wred[4][2];
    __shared__ int   s_islast;
    __shared__ unsigned s_tgt[BATCH];  // release targets for this replay
    // weights (any block may become a middle block)
    __shared__ float s_cw [BN * HDIM], s_cb [BN];
    __shared__ float s_ipw[3 * BN * BN], s_ipb[3 * BN];
    __shared__ float s_opw[BN * BN],  s_opb[BN];
    __shared__ float s_ew [HDIM * BN], s_eb [HDIM];
    __shared__ float s_lnw[HDIM], s_lnb[HDIM];
    __shared__ float s_gate;

    // snapshot release counters (before ANY arrival of this replay can release)
    if (t < BATCH) s_tgt[t] = *(volatile unsigned*)&g_done[t] + 1u;

    // weights -> smem
    if (t < BN * HDIM)   s_cw[t]  = cw[t];
    if (t < HDIM * BN)   s_ew[t]  = ew[t];
    if (t < 3 * BN * BN) s_ipw[t] = ipw[t];
    if (t < 3 * BN)      s_ipb[t] = ipb[t];
    if (t < BN * BN)     s_opw[t] = opw[t];
    if (t < BN)        { s_opb[t] = opb[t]; s_cb[t] = cb[t]; }
    if (t < HDIM)      { s_eb[t] = eb[t]; s_lnw[t] = lnw[t]; s_lnb[t] = lnb[t]; }
    if (t == 0)          s_gate = gate[0];
    __syncthreads();

    const float4* __restrict__ x4 = reinterpret_cast<const float4*>(x);
    float4*       __restrict__ o4 = reinterpret_cast<float4*>(out);

    // ---- write one batch's row: out = x(L2) + delta --------------------------
    auto write_row = [&](int j) {
        // wait for batch j's delta release (usually already set)
        if (t == 0) {
            while ((int)(*(volatile unsigned*)&g_done[j] - s_tgt[j]) < 0)
                __nanosleep(64);
            __threadfence();
        }
        __syncthreads();
        const size_t grow = (size_t)j * BROWS + bid;
        const float d = __ldcg(&g_delta[grow]);
        const float4* __restrict__ xr = x4 + grow * ROWQ;
        float4*       __restrict__ orow = o4 + grow * ROWQ;
#pragma unroll
        for (int i = 0; i < 4; i++) {
            float4 v = __ldcs(xr + t + i * TPB);   // L2-resident from pool(j)
            v.x += d; v.y += d; v.z += d; v.w += d;
            __stcs(orow + t + i * TPB, v);
        }
    };

    for (int b = 0; b < BATCH; b++) {
        // ---- pool row(b): default loads so lines persist in L2 ---------------
        const size_t grow = (size_t)b * BROWS + bid;
        const float4* __restrict__ xr = x4 + grow * ROWQ;
        float s = 0.f;
#pragma unroll
        for (int i = 0; i < 4; i++) {
            float4 v = xr[t + i * TPB];
            s += (v.x + v.y) + (v.z + v.w);
        }
#pragma unroll
        for (int off = 16; off; off >>= 1)
            s += __shfl_xor_sync(0xffffffffu, s, off);
        if ((t & 31) == 0) ws[t >> 5] = s;
        __syncthreads();
        if (t == 0) {
            float tot = 0.f;
#pragma unroll
            for (int w = 0; w < 8; w++) tot += ws[w];
            g_pooled[grow] = tot * (1.0f / (float)HW);
            __threadfence();
            unsigned old = atomicAdd(&g_cnt[b], 1u);
            s_islast = (old == BROWS - 1);
            if (s_islast) g_cnt[b] = 0;            // self-reset for next replay
        }
        __syncthreads();

        // ---- last arriver alone computes middle(b) ---------------------------
        if (s_islast) {
            if (t == 0) __threadfence();           // acquire others' pooled writes
            __syncthreads();
            const float* __restrict__ pb = g_pooled + (size_t)b * (LSEQ * HDIM);
#pragma unroll
            for (int i = 0; i < 4; i++)
                sp[t + i * TPB] = __ldcg(pb + t + i * TPB);
            __syncthreads();

            // compress: 64 outputs (l,e)
            if (t < LSEQ * BN) {
                const int l = t >> 2, e = t & 3;
                float acc = s_cb[e];
#pragma unroll 8
                for (int k = 0; k < HDIM; k++)
                    acc = fmaf(sp[l * HDIM + k], s_cw[e * HDIM + k], acc);
                s_xc[l][e] = acc;
            }
            __syncthreads();

            // qkv: 192 outputs
            if (t < LSEQ * 3 * BN) {
                const int l = t / (3 * BN), e = t % (3 * BN);
                float acc = s_ipb[e];
#pragma unroll
                for (int k = 0; k < BN; k++)
                    acc = fmaf(s_xc[l][k], s_ipw[e * BN + k], acc);
                s_qkv[l][e] = acc;
            }
            __syncthreads();

            // attention: 2 heads x 16 queries
            if (t < MHA_H * LSEQ) {
                const int h = t / LSEQ, q = t % LSEQ;
                const float scale = rsqrtf((float)DH);
                const float q0 = s_qkv[q][h * DH + 0];
                const float q1 = s_qkv[q][h * DH + 1];
                float m = -1e30f;
#pragma unroll
                for (int k = 0; k < LSEQ; k++) {
                    float sc = (q0 * s_qkv[k][BN + h * DH + 0] +
                                q1 * s_qkv[k][BN + h * DH + 1]) * scale;
                    s_sc[t][k] = sc;
                    m = fmaxf(m, sc);
                }
                float den = 0.f;
#pragma unroll
                for (int k = 0; k < LSEQ; k++) {
                    float e2 = __expf(s_sc[t][k] - m);
                    s_sc[t][k] = e2;
                    den += e2;
                }
                const float inv = 1.0f / den;
                float o0 = 0.f, o1 = 0.f;
#pragma unroll
                for (int k = 0; k < LSEQ; k++) {
                    const float a = s_sc[t][k] * inv;
                    o0 = fmaf(a, s_qkv[k][2 * BN + h * DH + 0], o0);
                    o1 = fmaf(a, s_qkv[k][2 * BN + h * DH + 1], o1);
                }
                s_ov[q][h * DH + 0] = o0;
                s_ov[q][h * DH + 1] = o1;
            }
            __syncthreads();

            // out_proj: 64 outputs
            if (t < LSEQ * BN) {
                const int l = t >> 2, e = t & 3;
                float acc = s_opb[e];
#pragma unroll
                for (int k = 0; k < BN; k++)
                    acc = fmaf(s_ov[l][k], s_opw[e * BN + k], acc);
                s_xat[l][e] = acc;
            }
            __syncthreads();

            // expand + residual + gate + LN for all 16 l (4 passes of 4 groups)
            const float g = s_gate;
            const int j = t & 63;
            const int grp = t >> 6;
#pragma unroll
            for (int pass = 0; pass < 4; pass++) {
                const int l = pass * 4 + grp;
                float xe = s_eb[j];
#pragma unroll
                for (int k = 0; k < BN; k++)
                    xe = fmaf(s_xat[l][k], s_ew[j * BN + k], xe);
                const float res = sp[l * HDIM + j];
                const float y = fmaf(g, xe, res);

                float sm = y;
#pragma unroll
                for (int off = 16; off; off >>= 1)
                    sm += __shfl_xor_sync(0xffffffffu, sm, off);
                if ((t & 31) == 0) wred[grp][(t >> 5) & 1] = sm;
                __syncthreads();
                const float mu = (wred[grp][0] + wred[grp][1]) * (1.0f / (float)HDIM);
                __syncthreads();

                const float dy = y - mu;
                float s2 = dy * dy;
#pragma unroll
                for (int off = 16; off; off >>= 1)
                    s2 += __shfl_xor_sync(0xffffffffu, s2, off);
                if ((t & 31) == 0) wred[grp][(t >> 5) & 1] = s2;
                __syncthreads();
                const float var = (wred[grp][0] + wred[grp][1]) * (1.0f / (float)HDIM);

                const float ln = dy * rsqrtf(var + 1e-5f) * s_lnw[j] + s_lnb[j];
                g_delta[(size_t)b * BROWS + l * HDIM + j] = ln - res;
                __syncthreads();
            }

            if (t == 0) {
                __threadfence();
                atomicAdd(&g_done[b], 1u);          // release batch b
            }
            __syncthreads();
        }

        // ---- lagged write: drain batch b-1 while batch b+1 pools next -------
        if (b >= 1) write_row(b - 1);
    }

    // tail
    write_row(BATCH - 1);
}

// ---------------------------------------------------------------------------
extern "C" void kernel_launch(void* const* d_in, const int* in_sizes, int n_in,
                              void* d_out, int out_size) {
    const float* x   = (const float*)d_in[0];
    const float* cw  = (const float*)d_in[1];
    const float* cb  = (const float*)d_in[2];
    const float* ipw = (const float*)d_in[3];
    const float* ipb = (const float*)d_in[4];
    const float* opw = (const float*)d_in[5];
    const float* opb = (const float*)d_in[6];
    const float* ew  = (const float*)d_in[7];
    const float* eb  = (const float*)d_in[8];
    const float* lnw = (const float*)d_in[9];
    const float* lnb = (const float*)d_in[10];
    const float* gt  = (const float*)d_in[11];
    float* out = (float*)d_out;

    fused_kernel<<<GRID, TPB>>>(x, out, cw, cb, ipw, ipb, opw, opb,
                                ew, eb, lnw, lnb, gt);
}

// round 16
// speedup vs baseline: 1.8703x; 1.5731x over previous
#include <cuda_runtime.h>
#include <cuda_bf16.h>

// Problem constants (fixed by reference setup_inputs)
#define BATCH   16
#define NHEAD   16
#define HDIM    64
#define HW      4096                   // H*W
#define ROWQ    (HW / 4)               // float4s per row = 1024
#define BROWS   (NHEAD * HDIM)         // rows per batch = 1024
#define NROWS   (BATCH * BROWS)        // 16384 rows
#define LSEQ    16                     // sequence length (= nH)
#define BN      4                      // bottleneck dim
#define MHA_H   2
#define DH      2

#define TPB     256

// Scratch + per-batch arrival counters (no allocations allowed)
__device__ float    g_pooled[NROWS];
__device__ float    g_delta [NROWS];
__device__ unsigned g_cnt   [BATCH];   // self-resetting, no one waits on these

// ---------------------------------------------------------------------------
// Kernel 1: pool every row; the LAST arriver of each batch (atomic counter)
// computes that batch's middle (compress->MHA->out_proj->expand->LN->delta).
// No block ever waits: pure streaming + one tiny detour for 16 blocks.
// ---------------------------------------------------------------------------
__global__ __launch_bounds__(TPB) void pool_middle_kernel(
    const float* __restrict__ x,
    const float* __restrict__ cw,  const float* __restrict__ cb,
    const float* __restrict__ ipw, const float* __restrict__ ipb,
    const float* __restrict__ opw, const float* __restrict__ opb,
    const float* __restrict__ ew,  const float* __restrict__ eb,
    const float* __restrict__ lnw, const float* __restrict__ lnb,
    const float* __restrict__ gate)
{
    const int grow = blockIdx.x;           // global row id
    const int b    = grow >> 10;           // batch
    const int t    = threadIdx.x;

    __shared__ float ws[8];
    __shared__ int   s_islast;

    // ---- pool: row mean (16 KB row, 4 float4 per thread) --------------------
    const float4* __restrict__ xr =
        reinterpret_cast<const float4*>(x) + (size_t)grow * ROWQ;
    float s = 0.f;
#pragma unroll
    for (int i = 0; i < 4; i++) {
        float4 v = xr[t + i * TPB];
        s += (v.x + v.y) + (v.z + v.w);
    }
#pragma unroll
    for (int off = 16; off; off >>= 1)
        s += __shfl_xor_sync(0xffffffffu, s, off);
    if ((t & 31) == 0) ws[t >> 5] = s;
    __syncthreads();
    if (t == 0) {
        float tot = 0.f;
#pragma unroll
        for (int w = 0; w < 8; w++) tot += ws[w];
        g_pooled[grow] = tot * (1.0f / (float)HW);
        __threadfence();                       // release pooled value
        unsigned old = atomicAdd(&g_cnt[b], 1u);
        s_islast = (old == BROWS - 1);
        if (s_islast) {
            g_cnt[b] = 0;                      // self-reset for graph replays
            __threadfence();                   // acquire others' pooled writes
        }
    }
    __syncthreads();
    if (!s_islast) return;                     // 16383 of 16384 blocks exit here

    // ======== middle for batch b (runs on exactly one block) =================
    __shared__ float sp   [LSEQ * HDIM];
    __shared__ float s_xc [LSEQ][BN];
    __shared__ float s_qkv[LSEQ][3 * BN];
    __shared__ float s_sc [MHA_H * LSEQ][LSEQ];
    __shared__ float s_ov [LSEQ][BN];
    __shared__ float s_xat[LSEQ][BN];
    __shared__ float wred [4][2];
    __shared__ float s_cw [BN * HDIM];
    __shared__ float s_ew [HDIM * BN];

    if (t < BN * HDIM) s_cw[t] = cw[t];
    if (t < HDIM * BN) s_ew[t] = ew[t];
    const float* __restrict__ pb = g_pooled + (size_t)b * (LSEQ * HDIM);
#pragma unroll
    for (int i = 0; i < 4; i++)
        sp[t + i * TPB] = __ldcg(pb + t + i * TPB);
    __syncthreads();

    // compress: 64 outputs (l,e)
    if (t < LSEQ * BN) {
        const int l = t >> 2, e = t & 3;
        float acc = cb[e];
#pragma unroll 8
        for (int k = 0; k < HDIM; k++)
            acc = fmaf(sp[l * HDIM + k], s_cw[e * HDIM + k], acc);
        s_xc[l][e] = acc;
    }
    __syncthreads();

    // qkv: 192 outputs
    if (t < LSEQ * 3 * BN) {
        const int l = t / (3 * BN), e = t % (3 * BN);
        float acc = ipb[e];
#pragma unroll
        for (int k = 0; k < BN; k++)
            acc = fmaf(s_xc[l][k], ipw[e * BN + k], acc);
        s_qkv[l][e] = acc;
    }
    __syncthreads();

    // attention: 2 heads x 16 queries
    if (t < MHA_H * LSEQ) {
        const int h = t / LSEQ, q = t % LSEQ;
        const float scale = rsqrtf((float)DH);
        const float q0 = s_qkv[q][h * DH + 0];
        const float q1 = s_qkv[q][h * DH + 1];
        float m = -1e30f;
#pragma unroll
        for (int k = 0; k < LSEQ; k++) {
            float sc = (q0 * s_qkv[k][BN + h * DH + 0] +
                        q1 * s_qkv[k][BN + h * DH + 1]) * scale;
            s_sc[t][k] = sc;
            m = fmaxf(m, sc);
        }
        float den = 0.f;
#pragma unroll
        for (int k = 0; k < LSEQ; k++) {
            float e2 = __expf(s_sc[t][k] - m);
            s_sc[t][k] = e2;
            den += e2;
        }
        const float inv = 1.0f / den;
        float o0 = 0.f, o1 = 0.f;
#pragma unroll
        for (int k = 0; k < LSEQ; k++) {
            const float a = s_sc[t][k] * inv;
            o0 = fmaf(a, s_qkv[k][2 * BN + h * DH + 0], o0);
            o1 = fmaf(a, s_qkv[k][2 * BN + h * DH + 1], o1);
        }
        s_ov[q][h * DH + 0] = o0;
        s_ov[q][h * DH + 1] = o1;
    }
    __syncthreads();

    // out_proj: 64 outputs
    if (t < LSEQ * BN) {
        const int l = t >> 2, e = t & 3;
        float acc = opb[e];
#pragma unroll
        for (int k = 0; k < BN; k++)
            acc = fmaf(s_ov[l][k], opw[e * BN + k], acc);
        s_xat[l][e] = acc;
    }
    __syncthreads();

    // expand + residual + gate + LN for all 16 l (4 passes x 4 groups of 64)
    const float g = gate[0];
    const int j   = t & 63;
    const int grp = t >> 6;
#pragma unroll
    for (int pass = 0; pass < 4; pass++) {
        const int l = pass * 4 + grp;
        float xe = eb[j];
#pragma unroll
        for (int k = 0; k < BN; k++)
            xe = fmaf(s_xat[l][k], s_ew[j * BN + k], xe);
        const float res = sp[l * HDIM + j];
        const float y = fmaf(g, xe, res);

        float sm = y;
#pragma unroll
        for (int off = 16; off; off >>= 1)
            sm += __shfl_xor_sync(0xffffffffu, sm, off);
        if ((t & 31) == 0) wred[grp][(t >> 5) & 1] = sm;
        __syncthreads();
        const float mu = (wred[grp][0] + wred[grp][1]) * (1.0f / (float)HDIM);
        __syncthreads();

        const float dy = y - mu;
        float s2 = dy * dy;
#pragma unroll
        for (int off = 16; off; off >>= 1)
            s2 += __shfl_xor_sync(0xffffffffu, s2, off);
        if ((t & 31) == 0) wred[grp][(t >> 5) & 1] = s2;
        __syncthreads();
        const float var = (wred[grp][0] + wred[grp][1]) * (1.0f / (float)HDIM);

        const float ln = dy * rsqrtf(var + 1e-5f) * lnw[j] + lnb[j];
        g_delta[(size_t)b * BROWS + l * HDIM + j] = ln - res;
        __syncthreads();
    }
}

// ---------------------------------------------------------------------------
// Kernel 2: out = x + delta[row]. Reverse row order (R1's proven 84% shape);
// __stcs on out (never re-read), __ldg broadcast for the delta scalar.
// ---------------------------------------------------------------------------
__global__ __launch_bounds__(TPB) void add_kernel(const float* __restrict__ x,
                                                  float* __restrict__ out) {
    const int row = (NROWS - 1) - blockIdx.x;
    const float d = __ldg(&g_delta[row]);
    const float4* __restrict__ xr =
        reinterpret_cast<const float4*>(x) + (size_t)row * ROWQ;
    float4* __restrict__ orow =
        reinterpret_cast<float4*>(out) + (size_t)row * ROWQ;

#pragma unroll
    for (int i = 0; i < 4; i++) {
        const int idx = threadIdx.x + i * TPB;
        float4 v = xr[idx];
        v.x += d; v.y += d; v.z += d; v.w += d;
        __stcs(orow + idx, v);
    }
}

// ---------------------------------------------------------------------------
extern "C" void kernel_launch(void* const* d_in, const int* in_sizes, int n_in,
                              void* d_out, int out_size) {
    const float* x   = (const float*)d_in[0];
    const float* cw  = (const float*)d_in[1];
    const float* cb  = (const float*)d_in[2];
    const float* ipw = (const float*)d_in[3];
    const float* ipb = (const float*)d_in[4];
    const float* opw = (const float*)d_in[5];
    const float* opb = (const float*)d_in[6];
    const float* ew  = (const float*)d_in[7];
    const float* eb  = (const float*)d_in[8];
    const float* lnw = (const float*)d_in[9];
    const float* lnb = (const float*)d_in[10];
    const float* gt  = (const float*)d_in[11];
    float* out = (float*)d_out;

    pool_middle_kernel<<<NROWS, TPB>>>(x, cw, cb, ipw, ipb, opw, opb,
                                       ew, eb, lnw, lnb, gt);
    add_kernel<<<NROWS, TPB>>>(x, out);
}